// round 1
// baseline (speedup 1.0000x reference)
#include <cuda_runtime.h>
#include <math.h>

// Problem constants
#define NIMG 48          // B*C = 16*3
#define N    512         // H = W
#define LOGN 9
#define KF   15          // PSF support
#define NC   8           // columns per block in column-FFT kernels
#define BALANCE 0.1f

// Scratch (device globals — no dynamic allocation allowed)
__device__ float2 g_Y[NIMG * N * N];      // full complex spectrum / image (100 MB)
__device__ float2 g_Tc[NIMG * KF * N];    // compact row-FFT of padded PSF (2.9 MB)

__device__ __forceinline__ int brev9(int x) { return (int)(__brev((unsigned)x) >> 23); }

__device__ __forceinline__ float2 cmul(float2 a, float2 b) {
    return make_float2(a.x * b.x - a.y * b.y, a.x * b.y + a.y * b.x);
}

// ---------------------------------------------------------------------------
// 512-point radix-2 DIT FFT on shared memory, 256 threads, 2 butterflies each.
// Input must be loaded bit-reversed: s[brev9(i)] = x[i]. Output natural order.
// tw[k] = exp(-2*pi*i*k/512), k in [0,256). SIGN=-1 forward, SIGN=+1 inverse.
// ---------------------------------------------------------------------------
template <int SIGN>
__device__ __forceinline__ void fft_row(float2* s, const float2* tw, int tid) {
#pragma unroll
    for (int st = 0; st < LOGN; st++) {
        __syncthreads();
        int half = 1 << st;
        int j    = tid & (half - 1);
        int i0   = ((tid >> st) << (st + 1)) | j;
        int i1   = i0 + half;
        float2 w = tw[j << (8 - st)];
        if (SIGN > 0) w.y = -w.y;
        float2 u = s[i0];
        float2 t = cmul(s[i1], w);
        s[i0] = make_float2(u.x + t.x, u.y + t.y);
        s[i1] = make_float2(u.x - t.x, u.y - t.y);
    }
    __syncthreads();
}

// Same FFT applied to NC interleaved columns: s is [512][NC], thread owns
// column c = tid & (NC-1), and 8 butterflies (bt, bt+32, ...) per stage.
template <int SIGN>
__device__ __forceinline__ void fft_col(float2* s, const float2* tw, int tid) {
    int c  = tid & (NC - 1);
    int bt = tid >> 3;
#pragma unroll
    for (int st = 0; st < LOGN; st++) {
        __syncthreads();
        int half = 1 << st;
#pragma unroll
        for (int bb = 0; bb < 8; bb++) {
            int b  = bt + bb * 32;
            int j  = b & (half - 1);
            int i0 = ((b >> st) << (st + 1)) | j;
            int i1 = i0 + half;
            float2 w = tw[j << (8 - st)];
            if (SIGN > 0) w.y = -w.y;
            float2 u = s[i0 * NC + c];
            float2 t = cmul(s[i1 * NC + c], w);
            s[i0 * NC + c] = make_float2(u.x + t.x, u.y + t.y);
            s[i1 * NC + c] = make_float2(u.x - t.x, u.y - t.y);
        }
    }
    __syncthreads();
}

__device__ __forceinline__ void fill_tw(float2* tw, int tid) {
    float sw, cw;
    sincosf(-3.14159265358979323846f * (float)tid / 256.0f, &sw, &cw);
    tw[tid] = make_float2(cw, sw);
}

// ---------------------------------------------------------------------------
// 1) Forward row FFT of y (real -> complex), one block per (image,row).
// ---------------------------------------------------------------------------
__global__ void kRowFwdY(const float* __restrict__ y) {
    __shared__ float2 s[N];
    __shared__ float2 tw[256];
    int tid = threadIdx.x;
    fill_tw(tw, tid);
    const float* yr = y + (size_t)blockIdx.x * N;
    s[brev9(tid)]       = make_float2(yr[tid], 0.0f);
    s[brev9(tid + 256)] = make_float2(yr[tid + 256], 0.0f);
    fft_row<-1>(s, tw, tid);
    float2* o = g_Y + (size_t)blockIdx.x * N;
    o[tid]       = s[tid];
    o[tid + 256] = s[tid + 256];
}

// ---------------------------------------------------------------------------
// 2) Column FFT of g_Y, in-place, 8 columns per block. SIGN=-1 fwd, +1 inv.
// ---------------------------------------------------------------------------
template <int SIGN>
__global__ void kColY() {
    __shared__ float2 s[N * NC];
    __shared__ float2 tw[256];
    int tid = threadIdx.x;
    fill_tw(tw, tid);
    int n    = blockIdx.x >> 6;   // image
    int tile = blockIdx.x & 63;   // 64 tiles of 8 columns
    float2* base = g_Y + (size_t)n * N * N + tile * NC;
    for (int idx = tid; idx < N * NC; idx += 256) {
        int c = idx & (NC - 1);
        int i = idx >> 3;
        s[brev9(i) * NC + c] = base[(size_t)i * N + c];
    }
    fft_col<SIGN>(s, tw, tid);
    for (int idx = tid; idx < N * NC; idx += 256) {
        int c = idx & (NC - 1);
        int i = idx >> 3;
        base[(size_t)i * N + c] = s[i * NC + c];
    }
}

// ---------------------------------------------------------------------------
// 3) Row FFT of the padded+rolled PSF. Only 15 of 512 rows are nonzero; we
//    FFT exactly those and store a compact [48][15][512] spectrum.
//    Padded row index i holds filter row r = (i+7) & 511 when r < 15; the
//    row content at column t is f[r][(t+7)&511] when that index < 15.
// ---------------------------------------------------------------------------
__global__ void kRowT(const float* __restrict__ filters) {
    __shared__ float2 s[N];
    __shared__ float2 tw[256];
    int tid = threadIdx.x;
    fill_tw(tw, tid);
    int n = blockIdx.x / KF;
    int r = blockIdx.x % KF;
    const float* f = filters + (size_t)(n * KF + r) * KF;
#pragma unroll
    for (int k = 0; k < 2; k++) {
        int t = tid + k * 256;
        int c = (t + 7) & 511;
        float v = (c < KF) ? f[c] : 0.0f;
        s[brev9(t)] = make_float2(v, 0.0f);
    }
    fft_row<-1>(s, tw, tid);
    float2* o = g_Tc + (size_t)blockIdx.x * N;
    o[tid]       = s[tid];
    o[tid + 256] = s[tid + 256];
}

// ---------------------------------------------------------------------------
// 4) Fused: column FFT of T (from 15-row-sparse compact buffer, never stored
//    to DRAM) + Wiener pointwise filter applied in-place to g_Y.
// ---------------------------------------------------------------------------
__global__ void kPointwise() {
    __shared__ float2 s[N * NC];
    __shared__ float2 tw[256];
    int tid = threadIdx.x;
    fill_tw(tw, tid);
    int n    = blockIdx.x >> 6;
    int tile = blockIdx.x & 63;
    int col0 = tile * NC;

    const float2* tc = g_Tc + (size_t)n * KF * N + col0;
    for (int idx = tid; idx < N * NC; idx += 256) {
        int c = idx & (NC - 1);
        int i = idx >> 3;
        int r = (i + 7) & 511;                    // filter row feeding padded row i
        float2 v = (r < KF) ? tc[(size_t)r * N + c] : make_float2(0.0f, 0.0f);
        s[brev9(i) * NC + c] = v;
    }
    fft_col<-1>(s, tw, tid);

    float2* base = g_Y + (size_t)n * N * N + col0;
    const float twopi_over_n = 6.283185307179586f / 512.0f;
    for (int idx = tid; idx < N * NC; idx += 256) {
        int c = idx & (NC - 1);
        int i = idx >> 3;
        float2 T  = s[i * NC + c];
        float2 Yv = base[(size_t)i * N + c];
        int jcol  = col0 + c;
        float reg = 4.0f - 2.0f * cosf(twopi_over_n * (float)i)
                         - 2.0f * cosf(twopi_over_n * (float)jcol);
        float denom = T.x * T.x + T.y * T.y + BALANCE * reg * reg;
        float inv = 1.0f / denom;
        float2 X;
        X.x = (T.x * Yv.x + T.y * Yv.y) * inv;   // conj(T) * Y / denom
        X.y = (T.x * Yv.y - T.y * Yv.x) * inv;
        base[(size_t)i * N + c] = X;
    }
}

// ---------------------------------------------------------------------------
// 5) Inverse row FFT + 1/N^2 scaling + clip, writing real part to output.
// ---------------------------------------------------------------------------
__global__ void kRowInv(float* __restrict__ out) {
    __shared__ float2 s[N];
    __shared__ float2 tw[256];
    int tid = threadIdx.x;
    fill_tw(tw, tid);
    const float2* in = g_Y + (size_t)blockIdx.x * N;
    s[brev9(tid)]       = in[tid];
    s[brev9(tid + 256)] = in[tid + 256];
    fft_row<1>(s, tw, tid);
    const float sc = 1.0f / (512.0f * 512.0f);
    float* o = out + (size_t)blockIdx.x * N;
    float v0 = s[tid].x * sc;
    float v1 = s[tid + 256].x * sc;
    o[tid]       = fminf(1.0f, fmaxf(-1.0f, v0));
    o[tid + 256] = fminf(1.0f, fmaxf(-1.0f, v1));
}

// ---------------------------------------------------------------------------
extern "C" void kernel_launch(void* const* d_in, const int* in_sizes, int n_in,
                              void* d_out, int out_size) {
    const float* y       = (const float*)d_in[0];   // [16,3,512,512]
    const float* filters = (const float*)d_in[1];   // [16,3,15,15]
    float* out = (float*)d_out;                      // [16,3,512,512]

    // Forward transform of y: rows then columns.
    kRowFwdY<<<NIMG * N, 256>>>(y);
    kColY<-1><<<NIMG * 64, 256>>>();

    // PSF spectrum rows (only 15 nonzero rows per image).
    kRowT<<<NIMG * KF, 256>>>(filters);

    // Fused T-column FFT + Wiener pointwise filter (in-place on spectrum).
    kPointwise<<<NIMG * 64, 256>>>();

    // Inverse transform: columns then rows (+ scale + clip + real output).
    kColY<1><<<NIMG * 64, 256>>>();
    kRowInv<<<NIMG * N, 256>>>(out);
}

// round 2
// speedup vs baseline: 1.6196x; 1.6196x over previous
#include <cuda_runtime.h>
#include <math.h>

// Problem constants
#define NIMG 48          // B*C = 16*3
#define N    512         // H = W
#define LOGN 9
#define KF   15          // PSF support
#define NC   8           // columns per block in column-FFT kernel
#define SP   9           // padded smem column stride (float2 units) -> no bank conflicts
#define W2   264         // padded half-spectrum width (257 used, multiple of 8)
#define NT   33          // column tiles of 8 (33*8 = 264)
#define BALANCE 0.1f

// Scratch (device globals — no dynamic allocation allowed)
__device__ float2 g_Y[NIMG * N * W2];     // half spectrum, padded stride (51.9 MB)
__device__ float2 g_Tc[NIMG * KF * W2];   // compact row-FFT of padded PSF (1.5 MB)

__device__ __forceinline__ int brev9(int x) { return (int)(__brev((unsigned)x) >> 23); }

__device__ __forceinline__ float2 cmul(float2 a, float2 b) {
    return make_float2(a.x * b.x - a.y * b.y, a.x * b.y + a.y * b.x);
}

__device__ __forceinline__ void fill_tw(float2* tw, int tid) {
    float sw, cw;
    sincosf(-3.14159265358979323846f * (float)tid / 256.0f, &sw, &cw);
    tw[tid] = make_float2(cw, sw);   // tw[k] = exp(-2*pi*i*k/512)
}

// ---------------------------------------------------------------------------
// Row FFTs: 512 points, 256 threads, 1 butterfly each per stage.
// DIT: bit-reversed input -> natural output. INV=1 conjugates twiddles.
// DIF: natural input -> bit-reversed output (forward only).
// ---------------------------------------------------------------------------
template <int INV>
__device__ __forceinline__ void fft_dit(float2* s, const float2* tw, int tid) {
#pragma unroll
    for (int st = 0; st < LOGN; st++) {
        __syncthreads();
        int half = 1 << st, j = tid & (half - 1);
        int i0 = ((tid >> st) << (st + 1)) | j, i1 = i0 + half;
        float2 w = tw[j << (8 - st)];
        if (INV) w.y = -w.y;
        float2 u = s[i0], t = cmul(s[i1], w);
        s[i0] = make_float2(u.x + t.x, u.y + t.y);
        s[i1] = make_float2(u.x - t.x, u.y - t.y);
    }
    __syncthreads();
}

__device__ __forceinline__ void fft_dif(float2* s, const float2* tw, int tid) {
#pragma unroll
    for (int st = LOGN - 1; st >= 0; st--) {
        __syncthreads();
        int half = 1 << st, j = tid & (half - 1);
        int i0 = ((tid >> st) << (st + 1)) | j, i1 = i0 + half;
        float2 w = tw[j << (8 - st)];
        float2 u = s[i0], v = s[i1];
        s[i0] = make_float2(u.x + v.x, u.y + v.y);
        s[i1] = cmul(make_float2(u.x - v.x, u.y - v.y), w);
    }
    __syncthreads();
}

// ---------------------------------------------------------------------------
// Column FFTs over 8 interleaved columns, smem stride SP=9 (conflict-free).
// Thread owns column c = tid&7 and butterflies bt, bt+32, ..., bt+224.
// ---------------------------------------------------------------------------
__device__ __forceinline__ void fft_col_dif(float2* s, const float2* tw, int tid) {
    int c = tid & 7, bt = tid >> 3;
    for (int st = LOGN - 1; st >= 0; st--) {
        __syncthreads();
        int half = 1 << st;
#pragma unroll
        for (int bb = 0; bb < 8; bb++) {
            int b = bt + bb * 32, j = b & (half - 1);
            int i0 = ((b >> st) << (st + 1)) | j, i1 = i0 + half;
            float2 w = tw[j << (8 - st)];
            float2 u = s[i0 * SP + c], v = s[i1 * SP + c];
            s[i0 * SP + c] = make_float2(u.x + v.x, u.y + v.y);
            s[i1 * SP + c] = cmul(make_float2(u.x - v.x, u.y - v.y), w);
        }
    }
    __syncthreads();
}

__device__ __forceinline__ void fft_col_dit_inv(float2* s, const float2* tw, int tid) {
    int c = tid & 7, bt = tid >> 3;
    for (int st = 0; st < LOGN; st++) {
        __syncthreads();
        int half = 1 << st;
#pragma unroll
        for (int bb = 0; bb < 8; bb++) {
            int b = bt + bb * 32, j = b & (half - 1);
            int i0 = ((b >> st) << (st + 1)) | j, i1 = i0 + half;
            float2 w = tw[j << (8 - st)];
            w.y = -w.y;
            float2 u = s[i0 * SP + c], t = cmul(s[i1 * SP + c], w);
            s[i0 * SP + c] = make_float2(u.x + t.x, u.y + t.y);
            s[i1 * SP + c] = make_float2(u.x - t.x, u.y - t.y);
        }
    }
    __syncthreads();
}

// ---------------------------------------------------------------------------
// 1) Forward row FFT of y: two real rows packed into one complex FFT (DIF),
//    Hermitian unpack, store half spectra (k = 0..256; pads 257..263 zeroed).
// ---------------------------------------------------------------------------
__global__ void kRowFwdY(const float* __restrict__ y) {
    __shared__ float2 s[N];
    __shared__ float2 tw[256];
    int tid = threadIdx.x;
    fill_tw(tw, tid);
    int n = blockIdx.x >> 8;      // image
    int rp = blockIdx.x & 255;    // row pair
    const float* y0 = y + ((size_t)n * N + 2 * rp) * N;
    const float* y1 = y0 + N;
    s[tid]       = make_float2(y0[tid], y1[tid]);
    s[tid + 256] = make_float2(y0[tid + 256], y1[tid + 256]);
    fft_dif(s, tw, tid);          // output bit-reversed
    float2* o0 = g_Y + ((size_t)n * N + 2 * rp) * W2;
    float2* o1 = o0 + W2;
    for (int k = tid; k < W2; k += 256) {
        float2 a, b;
        if (k <= 256) {
            int m = (N - k) & (N - 1);
            float2 Zk = s[brev9(k)];
            float2 Zm = s[brev9(m)];
            a = make_float2(0.5f * (Zk.x + Zm.x), 0.5f * (Zk.y - Zm.y));
            b = make_float2(0.5f * (Zk.y + Zm.y), 0.5f * (Zm.x - Zk.x));
        } else {
            a = make_float2(0.0f, 0.0f);
            b = make_float2(0.0f, 0.0f);
        }
        o0[k] = a;
        o1[k] = b;
    }
}

// ---------------------------------------------------------------------------
// 2) Row FFT of padded+rolled PSF rows (only 15 nonzero rows per image).
//    Natural-order output, store k = 0..256 (pads stay zero from .bss).
// ---------------------------------------------------------------------------
__global__ void kRowT(const float* __restrict__ filters) {
    __shared__ float2 s[N];
    __shared__ float2 tw[256];
    int tid = threadIdx.x;
    fill_tw(tw, tid);
    int n = blockIdx.x / KF, r = blockIdx.x % KF;
    const float* f = filters + (size_t)(n * KF + r) * KF;
#pragma unroll
    for (int k = 0; k < 2; k++) {
        int t = tid + k * 256;
        int c = (t + 7) & 511;
        float v = (c < KF) ? f[c] : 0.0f;
        s[brev9(t)] = make_float2(v, 0.0f);
    }
    fft_dit<0>(s, tw, tid);
    float2* o = g_Tc + (size_t)blockIdx.x * W2;
    for (int k = tid; k <= 256; k += 256) o[k] = s[k];
}

// ---------------------------------------------------------------------------
// 3) Fused column pass: fwd col FFT of T (sparse 15 rows -> registers),
//    fwd col FFT of Y, Wiener pointwise in bit-reversed order, inverse col
//    FFT, store. One read + one write of g_Y total.
// ---------------------------------------------------------------------------
__global__ void __launch_bounds__(256) kColFused() {
    __shared__ float2 s[N * SP];     // 36.9 KB
    __shared__ float2 tw[256];       // 2 KB
    __shared__ float  ctab[N];       // 2 KB: 2*cos(2*pi*v/512)
    int tid = threadIdx.x;
    fill_tw(tw, tid);
    ctab[tid]       = 2.0f * cosf(3.14159265358979323846f * (float)tid / 256.0f);
    ctab[tid + 256] = 2.0f * cosf(3.14159265358979323846f * (float)(tid + 256) / 256.0f);

    int n = blockIdx.x / NT;
    int tile = blockIdx.x % NT;
    int col0 = tile * NC;

    // Phase A: synthesize T columns (forward DIF), keep in registers.
    const float2* tc = g_Tc + (size_t)n * KF * W2 + col0;
#pragma unroll
    for (int k = 0; k < 16; k++) {
        int idx = tid + k * 256, c = idx & 7, i = idx >> 3;
        int r = (i + 7) & 511;   // filter row feeding padded row i
        float2 v = (r < KF) ? tc[(size_t)r * W2 + c] : make_float2(0.0f, 0.0f);
        s[i * SP + c] = v;
    }
    fft_col_dif(s, tw, tid);
    float2 T[16];
#pragma unroll
    for (int k = 0; k < 16; k++) {
        int idx = tid + k * 256, c = idx & 7, i = idx >> 3;
        T[k] = s[i * SP + c];
    }
    __syncthreads();

    // Phase B: Y forward, pointwise, inverse — single global round-trip.
    float2* base = g_Y + (size_t)n * N * W2 + col0;
#pragma unroll
    for (int k = 0; k < 16; k++) {
        int idx = tid + k * 256, c = idx & 7, i = idx >> 3;
        s[i * SP + c] = base[(size_t)i * W2 + c];
    }
    fft_col_dif(s, tw, tid);
#pragma unroll
    for (int k = 0; k < 16; k++) {
        int idx = tid + k * 256, c = idx & 7, i = idx >> 3;
        float2 Tv = T[k];
        float2 Yv = s[i * SP + c];
        int fr = brev9(i);           // true row frequency of this slot
        int jc = col0 + c;           // column frequency (natural)
        float reg = 4.0f - ctab[fr] - ctab[jc & 511];
        float inv = 1.0f / (Tv.x * Tv.x + Tv.y * Tv.y + BALANCE * reg * reg);
        s[i * SP + c] = make_float2((Tv.x * Yv.x + Tv.y * Yv.y) * inv,
                                    (Tv.x * Yv.y - Tv.y * Yv.x) * inv);
    }
    fft_col_dit_inv(s, tw, tid);
#pragma unroll
    for (int k = 0; k < 16; k++) {
        int idx = tid + k * 256, c = idx & 7, i = idx >> 3;
        base[(size_t)i * W2 + c] = s[i * SP + c];
    }
}

// ---------------------------------------------------------------------------
// 4) Inverse row FFT: rebuild two full Hermitian rows from half spectra,
//    one complex inverse FFT gives both real rows; scale + clip + store.
// ---------------------------------------------------------------------------
__global__ void kRowInv(float* __restrict__ out) {
    __shared__ float2 s[N];
    __shared__ float2 tw[256];
    __shared__ float2 hx0[257];
    __shared__ float2 hx1[257];
    int tid = threadIdx.x;
    fill_tw(tw, tid);
    int n = blockIdx.x >> 8, rp = blockIdx.x & 255;
    const float2* i0 = g_Y + ((size_t)n * N + 2 * rp) * W2;
    const float2* i1 = i0 + W2;
    for (int k = tid; k < 257; k += 256) { hx0[k] = i0[k]; hx1[k] = i1[k]; }
    __syncthreads();
#pragma unroll
    for (int kk = 0; kk < 2; kk++) {
        int k = tid + kk * 256;
        float2 a, b;
        if (k <= 256) { a = hx0[k]; b = hx1[k]; }
        else {
            int m = N - k;
            float2 am = hx0[m], bm = hx1[m];
            a = make_float2(am.x, -am.y);
            b = make_float2(bm.x, -bm.y);
        }
        // z(k) = X0(k) + i*X1(k)
        s[brev9(k)] = make_float2(a.x - b.y, a.y + b.x);
    }
    fft_dit<1>(s, tw, tid);
    const float sc = 1.0f / (512.0f * 512.0f);
    float* o0 = out + ((size_t)n * N + 2 * rp) * N;
    float* o1 = o0 + N;
#pragma unroll
    for (int kk = 0; kk < 2; kk++) {
        int t = tid + kk * 256;
        float2 v = s[t];
        o0[t] = fminf(1.0f, fmaxf(-1.0f, v.x * sc));
        o1[t] = fminf(1.0f, fmaxf(-1.0f, v.y * sc));
    }
}

// ---------------------------------------------------------------------------
extern "C" void kernel_launch(void* const* d_in, const int* in_sizes, int n_in,
                              void* d_out, int out_size) {
    const float* y       = (const float*)d_in[0];   // [16,3,512,512]
    const float* filters = (const float*)d_in[1];   // [16,3,15,15]
    float* out = (float*)d_out;                      // [16,3,512,512]

    kRowFwdY<<<NIMG * 256, 256>>>(y);        // rows: 2 real rows per FFT
    kRowT<<<NIMG * KF, 256>>>(filters);      // sparse PSF row spectra
    kColFused<<<NIMG * NT, 256>>>();         // fwd col + Wiener + inv col
    kRowInv<<<NIMG * 256, 256>>>(out);       // inverse rows, 2 per FFT
}

// round 3
// speedup vs baseline: 5.6436x; 3.4846x over previous
#include <cuda_runtime.h>
#include <math.h>

#define NIMG 48
#define N    512
#define KF   15
#define W2   264          // padded half-spectrum width (257 used)
#define NT   33           // 33 tiles of 8 columns = 264
#define BALANCE 0.1f
#define S2C 0.70710678118654752f
#define PADI(n) ((n) + ((n) >> 3))   // pad 1 per 8 -> region size <= 575

__device__ float2 g_Y[NIMG * N * W2];     // half spectrum (51.9 MB)
__device__ float2 g_Tc[NIMG * KF * W2];   // PSF row spectra (1.5 MB)

__device__ __forceinline__ int brev9(int x) { return (int)(__brev((unsigned)x) >> 23); }
__device__ __forceinline__ int brev6(int x) { return (int)(__brev((unsigned)x) >> 26); }
__device__ __forceinline__ float2 cmul(float2 a, float2 b) {
    return make_float2(a.x * b.x - a.y * b.y, a.x * b.y + a.y * b.x);
}
__device__ __forceinline__ float2 cadd(float2 a, float2 b) { return make_float2(a.x + b.x, a.y + b.y); }
__device__ __forceinline__ float2 csub(float2 a, float2 b) { return make_float2(a.x - b.x, a.y - b.y); }

// ---------------------------------------------------------------------------
// Register radix-8 building blocks. dif8 = 3 radix-2 DIF stages (spans 4,2,1
// in units of r) with base twiddle w1 = W^e (W = exp(-2*pi*i/512)):
//   span4 twiddles w1*W^{64r}, span2 w1^2 (*W^128 for odd), span1 w1^4.
// dit8 is the exact inverse mirror (pass w1 = conj base).
// ---------------------------------------------------------------------------
template <bool TW>
__device__ __forceinline__ void dif8(float2 v[8], float2 w1) {
    float2 w2, w4;
    if (TW) { w2 = cmul(w1, w1); w4 = cmul(w2, w2); }
    float2 t0 = csub(v[0], v[4]); v[0] = cadd(v[0], v[4]);
    float2 t1 = csub(v[1], v[5]); v[1] = cadd(v[1], v[5]);
    float2 t2 = csub(v[2], v[6]); v[2] = cadd(v[2], v[6]);
    float2 t3 = csub(v[3], v[7]); v[3] = cadd(v[3], v[7]);
    t1 = make_float2(S2C * (t1.x + t1.y), S2C * (t1.y - t1.x));   // * (s,-s)
    t2 = make_float2(t2.y, -t2.x);                                 // * (0,-1)
    t3 = make_float2(S2C * (t3.y - t3.x), -S2C * (t3.x + t3.y));   // * (-s,-s)
    if (TW) { t0 = cmul(t0, w1); t1 = cmul(t1, w1); t2 = cmul(t2, w1); t3 = cmul(t3, w1); }
    v[4] = t0; v[5] = t1; v[6] = t2; v[7] = t3;
    float2 t;
    t = csub(v[0], v[2]); v[0] = cadd(v[0], v[2]); if (TW) t = cmul(t, w2); v[2] = t;
    t = csub(v[1], v[3]); v[1] = cadd(v[1], v[3]); t = make_float2(t.y, -t.x); if (TW) t = cmul(t, w2); v[3] = t;
    t = csub(v[4], v[6]); v[4] = cadd(v[4], v[6]); if (TW) t = cmul(t, w2); v[6] = t;
    t = csub(v[5], v[7]); v[5] = cadd(v[5], v[7]); t = make_float2(t.y, -t.x); if (TW) t = cmul(t, w2); v[7] = t;
    t = csub(v[0], v[1]); v[0] = cadd(v[0], v[1]); if (TW) t = cmul(t, w4); v[1] = t;
    t = csub(v[2], v[3]); v[2] = cadd(v[2], v[3]); if (TW) t = cmul(t, w4); v[3] = t;
    t = csub(v[4], v[5]); v[4] = cadd(v[4], v[5]); if (TW) t = cmul(t, w4); v[5] = t;
    t = csub(v[6], v[7]); v[6] = cadd(v[6], v[7]); if (TW) t = cmul(t, w4); v[7] = t;
}

template <bool TW>
__device__ __forceinline__ void dit8(float2 v[8], float2 w1) {
    float2 w2, w4;
    if (TW) { w2 = cmul(w1, w1); w4 = cmul(w2, w2); }
    float2 t;
    t = v[1]; if (TW) t = cmul(t, w4); v[1] = csub(v[0], t); v[0] = cadd(v[0], t);
    t = v[3]; if (TW) t = cmul(t, w4); v[3] = csub(v[2], t); v[2] = cadd(v[2], t);
    t = v[5]; if (TW) t = cmul(t, w4); v[5] = csub(v[4], t); v[4] = cadd(v[4], t);
    t = v[7]; if (TW) t = cmul(t, w4); v[7] = csub(v[6], t); v[6] = cadd(v[6], t);
    t = v[2]; if (TW) t = cmul(t, w2); v[2] = csub(v[0], t); v[0] = cadd(v[0], t);
    t = v[3]; t = make_float2(-t.y, t.x); if (TW) t = cmul(t, w2); v[3] = csub(v[1], t); v[1] = cadd(v[1], t);
    t = v[6]; if (TW) t = cmul(t, w2); v[6] = csub(v[4], t); v[4] = cadd(v[4], t);
    t = v[7]; t = make_float2(-t.y, t.x); if (TW) t = cmul(t, w2); v[7] = csub(v[5], t); v[5] = cadd(v[5], t);
    t = v[4]; if (TW) t = cmul(t, w1); v[4] = csub(v[0], t); v[0] = cadd(v[0], t);
    t = v[5]; t = make_float2(S2C * (t.x - t.y), S2C * (t.x + t.y)); if (TW) t = cmul(t, w1);   // * (s,s)
    v[5] = csub(v[1], t); v[1] = cadd(v[1], t);
    t = v[6]; t = make_float2(-t.y, t.x); if (TW) t = cmul(t, w1);                              // * (0,1)
    v[6] = csub(v[2], t); v[2] = cadd(v[2], t);
    t = v[7]; t = make_float2(-S2C * (t.x + t.y), S2C * (t.x - t.y)); if (TW) t = cmul(t, w1);  // * (-s,s)
    v[7] = csub(v[3], t); v[3] = cadd(v[3], t);
}

__device__ __forceinline__ float2 wang(float a) {   // exp(i*a)
    float sn, cs; sincosf(a, &sn, &cs); return make_float2(cs, sn);
}
#define ANG (-3.14159265358979323846f)

// Full forward 512-pt FFT over one shared region (per-thread lane q in [0,64)).
// v enters as x[q+64r]; exits holding X slots at positions 8q+r (bit-reversed
// spectrum: pos p holds freq brev9(p)). Uses 2 shared exchanges.
__device__ __forceinline__ void fwd512(float2 v[8], float2* sh, int q) {
    dif8<true>(v, wang(ANG * (float)q / 256.0f));
#pragma unroll
    for (int r = 0; r < 8; r++) sh[PADI(q + 64 * r)] = v[r];
    __syncthreads();
    int b = q >> 3, q2 = q & 7;
#pragma unroll
    for (int r = 0; r < 8; r++) v[r] = sh[PADI(64 * b + q2 + 8 * r)];
    dif8<true>(v, wang(ANG * (float)q2 / 32.0f));
#pragma unroll
    for (int r = 0; r < 8; r++) sh[PADI(64 * b + q2 + 8 * r)] = v[r];
    __syncthreads();
#pragma unroll
    for (int r = 0; r < 8; r++) v[r] = sh[PADI(8 * q + r)];
    dif8<false>(v, make_float2(1.0f, 0.0f));
}

// ---------------------------------------------------------------------------
// 1) Forward row FFT of y: 2 real rows packed per complex FFT; 4 FFTs/block.
// ---------------------------------------------------------------------------
__global__ void __launch_bounds__(256) kRowFwdY(const float* __restrict__ y) {
    __shared__ float2 sh[4][576];
    int tid = threadIdx.x, q = tid & 63, sub = tid >> 6;
    int g = blockIdx.x * 4 + sub;              // row-pair id
    int n = g >> 8, rp = g & 255;
    const float* y0 = y + ((size_t)n * N + 2 * rp) * N;
    const float* y1 = y0 + N;
    float2 v[8];
#pragma unroll
    for (int r = 0; r < 8; r++) { int i = q + 64 * r; v[r] = make_float2(y0[i], y1[i]); }
    fwd512(v, sh[sub], q);
#pragma unroll
    for (int r = 0; r < 8; r++) sh[sub][PADI(8 * q + r)] = v[r];
    __syncthreads();
    float2* o0 = g_Y + ((size_t)n * N + 2 * rp) * W2;
    float2* o1 = o0 + W2;
#pragma unroll
    for (int kk = 0; kk < 5; kk++) {
        int k = q + kk * 64;
        if (k >= W2) break;
        float2 a, b;
        if (k <= 256) {
            int m = (N - k) & (N - 1);
            float2 Zk = sh[sub][PADI(brev9(k))];
            float2 Zm = sh[sub][PADI(brev9(m))];
            a = make_float2(0.5f * (Zk.x + Zm.x), 0.5f * (Zk.y - Zm.y));
            b = make_float2(0.5f * (Zk.y + Zm.y), 0.5f * (Zm.x - Zk.x));
        } else { a = make_float2(0.f, 0.f); b = a; }
        o0[k] = a; o1[k] = b;
    }
}

// ---------------------------------------------------------------------------
// 2) Row FFT of padded+rolled PSF rows (15 nonzero rows/image); 4 rows/block.
// ---------------------------------------------------------------------------
__global__ void __launch_bounds__(256) kRowT(const float* __restrict__ filters) {
    __shared__ float2 sh[4][576];
    int tid = threadIdx.x, q = tid & 63, sub = tid >> 6;
    int g = blockIdx.x * 4 + sub;              // 0 .. 719
    int n = g / KF, r0 = g % KF;
    const float* f = filters + (size_t)(n * KF + r0) * KF;
    float2 v[8];
#pragma unroll
    for (int r = 0; r < 8; r++) {
        int c = (q + 64 * r + 7) & 511;
        float val = (c < KF) ? f[c] : 0.0f;
        v[r] = make_float2(val, 0.0f);
    }
    fwd512(v, sh[sub], q);
#pragma unroll
    for (int r = 0; r < 8; r++) sh[sub][PADI(8 * q + r)] = v[r];
    __syncthreads();
    float2* o = g_Tc + (size_t)g * W2;
#pragma unroll
    for (int kk = 0; kk < 5; kk++) {
        int k = q + kk * 64;
        if (k > 256) break;
        o[k] = sh[sub][PADI(brev9(k))];
    }
}

// ---------------------------------------------------------------------------
// 3) Fused column pass: T column synthesis (sparse, registers) + Y fwd col
//    FFT + Wiener pointwise + inverse col FFT. 8 columns/block, 512 threads.
// ---------------------------------------------------------------------------
__global__ void __launch_bounds__(512) kColFused() {
    __shared__ float2 sh[575 * 8];
    __shared__ float ctab[512];
    int tid = threadIdx.x, c = tid & 7, t = tid >> 3;   // t in [0,64)
    ctab[tid] = 2.0f * cosf(3.14159265358979323846f * (float)tid / 256.0f);
    int n = blockIdx.x / NT, tile = blockIdx.x % NT;
    int col0 = tile * 8;
    int b = t >> 3, q2 = t & 7;

    // ---- T: sparse register load + forward column FFT ----
    const float2* tc = g_Tc + (size_t)n * KF * W2 + col0 + c;
    float2 v[8];
#pragma unroll
    for (int r = 0; r < 8; r++) {
        int rr = (t + 64 * r + 7) & 511;
        v[r] = (rr < KF) ? tc[(size_t)rr * W2] : make_float2(0.0f, 0.0f);
    }
    dif8<true>(v, wang(ANG * (float)t / 256.0f));
#pragma unroll
    for (int r = 0; r < 8; r++) sh[PADI(t + 64 * r) * 8 + c] = v[r];
    __syncthreads();
#pragma unroll
    for (int r = 0; r < 8; r++) v[r] = sh[PADI(64 * b + q2 + 8 * r) * 8 + c];
    dif8<true>(v, wang(ANG * (float)q2 / 32.0f));
#pragma unroll
    for (int r = 0; r < 8; r++) sh[PADI(64 * b + q2 + 8 * r) * 8 + c] = v[r];
    __syncthreads();
    float2 T[8];
#pragma unroll
    for (int r = 0; r < 8; r++) T[r] = sh[PADI(8 * t + r) * 8 + c];
    dif8<false>(T, make_float2(1.0f, 0.0f));

    // ---- Y forward column FFT (group 1 overlaps with T group-3 reads) ----
    float2* base = g_Y + (size_t)n * N * W2 + col0 + c;
#pragma unroll
    for (int r = 0; r < 8; r++) v[r] = base[(size_t)(t + 64 * r) * W2];
    dif8<true>(v, wang(ANG * (float)t / 256.0f));
    __syncthreads();                     // all T reads done before overwrite
#pragma unroll
    for (int r = 0; r < 8; r++) sh[PADI(t + 64 * r) * 8 + c] = v[r];
    __syncthreads();
#pragma unroll
    for (int r = 0; r < 8; r++) v[r] = sh[PADI(64 * b + q2 + 8 * r) * 8 + c];
    dif8<true>(v, wang(ANG * (float)q2 / 32.0f));
#pragma unroll
    for (int r = 0; r < 8; r++) sh[PADI(64 * b + q2 + 8 * r) * 8 + c] = v[r];
    __syncthreads();
#pragma unroll
    for (int r = 0; r < 8; r++) v[r] = sh[PADI(8 * t + r) * 8 + c];
    dif8<false>(v, make_float2(1.0f, 0.0f));

    // ---- Wiener pointwise (bit-reversed slots match between T and Y) ----
    int kb6 = brev6(t);
    float cj = ctab[col0 + c];
#pragma unroll
    for (int r = 0; r < 8; r++) {
        int fr = 64 * (((r & 1) << 2) | (r & 2) | (r >> 2)) + kb6;
        float reg = 4.0f - ctab[fr] - cj;
        float2 Tv = T[r], Yv = v[r];
        float inv = 1.0f / (Tv.x * Tv.x + Tv.y * Tv.y + BALANCE * reg * reg);
        v[r] = make_float2((Tv.x * Yv.x + Tv.y * Yv.y) * inv,
                           (Tv.x * Yv.y - Tv.y * Yv.x) * inv);
    }

    // ---- inverse column FFT (group 1 directly on pointwise registers) ----
    dit8<false>(v, make_float2(1.0f, 0.0f));
    __syncthreads();
#pragma unroll
    for (int r = 0; r < 8; r++) sh[PADI(8 * t + r) * 8 + c] = v[r];
    __syncthreads();
#pragma unroll
    for (int r = 0; r < 8; r++) v[r] = sh[PADI(64 * b + q2 + 8 * r) * 8 + c];
    dit8<true>(v, wang(-ANG * (float)q2 / 32.0f));
#pragma unroll
    for (int r = 0; r < 8; r++) sh[PADI(64 * b + q2 + 8 * r) * 8 + c] = v[r];
    __syncthreads();
#pragma unroll
    for (int r = 0; r < 8; r++) v[r] = sh[PADI(t + 64 * r) * 8 + c];
    dit8<true>(v, wang(-ANG * (float)t / 256.0f));
#pragma unroll
    for (int r = 0; r < 8; r++) base[(size_t)(t + 64 * r) * W2] = v[r];
}

// ---------------------------------------------------------------------------
// 4) Inverse row FFT: Hermitian rebuild of 2 rows -> 1 complex inverse FFT;
//    scale + clip + store. 4 row-pairs/block.
// ---------------------------------------------------------------------------
__global__ void __launch_bounds__(256) kRowInv(float* __restrict__ out) {
    __shared__ float2 sh[4][576];            // staged as hx0[0..256], hx1[257..513], then FFT
    int tid = threadIdx.x, q = tid & 63, sub = tid >> 6;
    int g = blockIdx.x * 4 + sub;
    int n = g >> 8, rp = g & 255;
    const float2* i0 = g_Y + ((size_t)n * N + 2 * rp) * W2;
    const float2* i1 = i0 + W2;
    for (int k = q; k < 257; k += 64) { sh[sub][k] = i0[k]; sh[sub][257 + k] = i1[k]; }
    __syncthreads();
    // Build z at input positions p = 8q + r (freq brev9(p)) directly in regs.
    int kb6 = brev6(q);
    float2 v[8];
#pragma unroll
    for (int r = 0; r < 8; r++) {
        int k = kb6 + 64 * (((r & 1) << 2) | (r & 2) | (r >> 2));
        float2 a, bb;
        if (k <= 256) { a = sh[sub][k]; bb = sh[sub][257 + k]; }
        else {
            int m = N - k;
            float2 am = sh[sub][m], bm = sh[sub][257 + m];
            a = make_float2(am.x, -am.y); bb = make_float2(bm.x, -bm.y);
        }
        v[r] = make_float2(a.x - bb.y, a.y + bb.x);   // z = X0 + i*X1
    }
    dit8<false>(v, make_float2(1.0f, 0.0f));
    __syncthreads();                                  // all gathers done
#pragma unroll
    for (int r = 0; r < 8; r++) sh[sub][PADI(8 * q + r)] = v[r];
    __syncthreads();
    int b = q >> 3, q2 = q & 7;
#pragma unroll
    for (int r = 0; r < 8; r++) v[r] = sh[sub][PADI(64 * b + q2 + 8 * r)];
    dit8<true>(v, wang(-ANG * (float)q2 / 32.0f));
#pragma unroll
    for (int r = 0; r < 8; r++) sh[sub][PADI(64 * b + q2 + 8 * r)] = v[r];
    __syncthreads();
    const float sc = 1.0f / (512.0f * 512.0f);
    float* o0 = out + ((size_t)n * N + 2 * rp) * N;
    float* o1 = o0 + N;
#pragma unroll
    for (int r = 0; r < 8; r++) v[r] = sh[sub][PADI(q + 64 * r)];
    dit8<true>(v, wang(-ANG * (float)q / 256.0f));
#pragma unroll
    for (int r = 0; r < 8; r++) {
        int i = q + 64 * r;
        o0[i] = fminf(1.0f, fmaxf(-1.0f, v[r].x * sc));
        o1[i] = fminf(1.0f, fmaxf(-1.0f, v[r].y * sc));
    }
}

// ---------------------------------------------------------------------------
extern "C" void kernel_launch(void* const* d_in, const int* in_sizes, int n_in,
                              void* d_out, int out_size) {
    const float* y       = (const float*)d_in[0];
    const float* filters = (const float*)d_in[1];
    float* out = (float*)d_out;

    kRowFwdY<<<NIMG * 64, 256>>>(y);        // 12288 row-pairs / 4 per block
    kRowT<<<180, 256>>>(filters);           // 720 PSF rows / 4 per block
    kColFused<<<NIMG * NT, 512>>>();        // fwd col + Wiener + inv col
    kRowInv<<<NIMG * 64, 256>>>(out);       // 12288 row-pairs / 4 per block
}

// round 4
// speedup vs baseline: 6.2279x; 1.1035x over previous
#include <cuda_runtime.h>
#include <math.h>

#define NIMG 48
#define N    512
#define KF   15
#define W2   264          // g_Tc padded width (cols 0..256 used)
#define BALANCE 0.1f
#define S2C 0.70710678118654752f
#define PI  3.14159265358979323846f
#define ANG (-3.14159265358979323846f)
#define PADI(n) ((n) + ((n) >> 3))

// Packed spectrum, slot-ordered: g_Z[n][rp][p] = Z[rp, brev9(p)] where
// Z[rp] = FFT(y[2rp] + i*y[2rp+1]).  50.3 MB, updated in place by kColPair.
__device__ __align__(256) float2 g_Z[NIMG * 256 * 512];
__device__ __align__(256) float2 g_Tc[NIMG * KF * W2];   // PSF row spectra

// Tile pairs: mate(a) = brev6(64 - brev6(a)); 2 self-pairs + 31 proper = 33.
__constant__ int2 PAIRS[33] = {
    {0,0},{1,1},{2,3},{4,7},{5,6},{8,15},{9,14},{10,13},{11,12},
    {16,31},{17,30},{18,29},{19,28},{20,27},{21,26},{22,25},{23,24},
    {32,63},{33,62},{34,61},{35,60},{36,59},{37,58},{38,57},{39,56},
    {40,55},{41,54},{42,53},{43,52},{44,51},{45,50},{46,49},{47,48}
};

__device__ __forceinline__ int brev9(int x) { return (int)(__brev((unsigned)x) >> 23); }
__device__ __forceinline__ int brev6(int x) { return (int)(__brev((unsigned)x) >> 26); }
__device__ __forceinline__ int brev3v(int x) { return ((x & 1) << 2) | (x & 2) | (x >> 2); }
__device__ __forceinline__ float2 cmul(float2 a, float2 b) {
    return make_float2(a.x * b.x - a.y * b.y, a.x * b.y + a.y * b.x);
}
__device__ __forceinline__ float2 cadd(float2 a, float2 b) { return make_float2(a.x + b.x, a.y + b.y); }
__device__ __forceinline__ float2 csub(float2 a, float2 b) { return make_float2(a.x - b.x, a.y - b.y); }
__device__ __forceinline__ float2 wang(float a) { float sn, cs; sincosf(a, &sn, &cs); return make_float2(cs, sn); }

// ---------------------------------------------------------------------------
// Register radix-8 blocks (3 radix-2 stages). Same math as R3.
// ---------------------------------------------------------------------------
template <bool TW>
__device__ __forceinline__ void dif8(float2 v[8], float2 w1) {
    float2 w2, w4;
    if (TW) { w2 = cmul(w1, w1); w4 = cmul(w2, w2); }
    float2 t0 = csub(v[0], v[4]); v[0] = cadd(v[0], v[4]);
    float2 t1 = csub(v[1], v[5]); v[1] = cadd(v[1], v[5]);
    float2 t2 = csub(v[2], v[6]); v[2] = cadd(v[2], v[6]);
    float2 t3 = csub(v[3], v[7]); v[3] = cadd(v[3], v[7]);
    t1 = make_float2(S2C * (t1.x + t1.y), S2C * (t1.y - t1.x));
    t2 = make_float2(t2.y, -t2.x);
    t3 = make_float2(S2C * (t3.y - t3.x), -S2C * (t3.x + t3.y));
    if (TW) { t0 = cmul(t0, w1); t1 = cmul(t1, w1); t2 = cmul(t2, w1); t3 = cmul(t3, w1); }
    v[4] = t0; v[5] = t1; v[6] = t2; v[7] = t3;
    float2 t;
    t = csub(v[0], v[2]); v[0] = cadd(v[0], v[2]); if (TW) t = cmul(t, w2); v[2] = t;
    t = csub(v[1], v[3]); v[1] = cadd(v[1], v[3]); t = make_float2(t.y, -t.x); if (TW) t = cmul(t, w2); v[3] = t;
    t = csub(v[4], v[6]); v[4] = cadd(v[4], v[6]); if (TW) t = cmul(t, w2); v[6] = t;
    t = csub(v[5], v[7]); v[5] = cadd(v[5], v[7]); t = make_float2(t.y, -t.x); if (TW) t = cmul(t, w2); v[7] = t;
    t = csub(v[0], v[1]); v[0] = cadd(v[0], v[1]); if (TW) t = cmul(t, w4); v[1] = t;
    t = csub(v[2], v[3]); v[2] = cadd(v[2], v[3]); if (TW) t = cmul(t, w4); v[3] = t;
    t = csub(v[4], v[5]); v[4] = cadd(v[4], v[5]); if (TW) t = cmul(t, w4); v[5] = t;
    t = csub(v[6], v[7]); v[6] = cadd(v[6], v[7]); if (TW) t = cmul(t, w4); v[7] = t;
}

template <bool TW>
__device__ __forceinline__ void dit8(float2 v[8], float2 w1) {
    float2 w2, w4;
    if (TW) { w2 = cmul(w1, w1); w4 = cmul(w2, w2); }
    float2 t;
    t = v[1]; if (TW) t = cmul(t, w4); v[1] = csub(v[0], t); v[0] = cadd(v[0], t);
    t = v[3]; if (TW) t = cmul(t, w4); v[3] = csub(v[2], t); v[2] = cadd(v[2], t);
    t = v[5]; if (TW) t = cmul(t, w4); v[5] = csub(v[4], t); v[4] = cadd(v[4], t);
    t = v[7]; if (TW) t = cmul(t, w4); v[7] = csub(v[6], t); v[6] = cadd(v[6], t);
    t = v[2]; if (TW) t = cmul(t, w2); v[2] = csub(v[0], t); v[0] = cadd(v[0], t);
    t = v[3]; t = make_float2(-t.y, t.x); if (TW) t = cmul(t, w2); v[3] = csub(v[1], t); v[1] = cadd(v[1], t);
    t = v[6]; if (TW) t = cmul(t, w2); v[6] = csub(v[4], t); v[4] = cadd(v[4], t);
    t = v[7]; t = make_float2(-t.y, t.x); if (TW) t = cmul(t, w2); v[7] = csub(v[5], t); v[5] = cadd(v[5], t);
    t = v[4]; if (TW) t = cmul(t, w1); v[4] = csub(v[0], t); v[0] = cadd(v[0], t);
    t = v[5]; t = make_float2(S2C * (t.x - t.y), S2C * (t.x + t.y)); if (TW) t = cmul(t, w1);
    v[5] = csub(v[1], t); v[1] = cadd(v[1], t);
    t = v[6]; t = make_float2(-t.y, t.x); if (TW) t = cmul(t, w1);
    v[6] = csub(v[2], t); v[2] = cadd(v[2], t);
    t = v[7]; t = make_float2(-S2C * (t.x + t.y), S2C * (t.x - t.y)); if (TW) t = cmul(t, w1);
    v[7] = csub(v[3], t); v[3] = cadd(v[3], t);
}

// Forward 512-pt FFT: v enters x[q+64r], exits slot 8q+r (slot p = freq brev9(p)).
__device__ __forceinline__ void fwd512(float2 v[8], float2* sh, int q) {
    dif8<true>(v, wang(ANG * (float)q / 256.0f));
#pragma unroll
    for (int r = 0; r < 8; r++) sh[PADI(q + 64 * r)] = v[r];
    __syncthreads();
    int b = q >> 3, q2 = q & 7;
#pragma unroll
    for (int r = 0; r < 8; r++) v[r] = sh[PADI(64 * b + q2 + 8 * r)];
    dif8<true>(v, wang(ANG * (float)q2 / 32.0f));
#pragma unroll
    for (int r = 0; r < 8; r++) sh[PADI(64 * b + q2 + 8 * r)] = v[r];
    __syncthreads();
#pragma unroll
    for (int r = 0; r < 8; r++) v[r] = sh[PADI(8 * q + r)];
    dif8<false>(v, make_float2(1.0f, 0.0f));
}

// ---------------------------------------------------------------------------
// 1) kRowFwdY: 2 real rows per complex FFT, packed spectrum stored slot-order
//    directly from registers (float4, fully coalesced). No Hermitian pass.
// ---------------------------------------------------------------------------
__global__ void __launch_bounds__(256) kRowFwdY(const float* __restrict__ y) {
    __shared__ float2 sh[4][576];
    int tid = threadIdx.x, q = tid & 63, sub = tid >> 6;
    int g = blockIdx.x * 4 + sub;              // global row-pair id
    int n = g >> 8, rp = g & 255;
    const float* y0 = y + ((size_t)n * N + 2 * rp) * N;
    const float* y1 = y0 + N;
    float2 v[8];
#pragma unroll
    for (int r = 0; r < 8; r++) { int i = q + 64 * r; v[r] = make_float2(y0[i], y1[i]); }
    fwd512(v, sh[sub], q);
    float4* o = reinterpret_cast<float4*>(g_Z + (size_t)g * 512 + 8 * q);
#pragma unroll
    for (int r = 0; r < 4; r++)
        o[r] = make_float4(v[2 * r].x, v[2 * r].y, v[2 * r + 1].x, v[2 * r + 1].y);
}

// ---------------------------------------------------------------------------
// 2) kRowT: PSF row spectra (15 nonzero rows/image), natural freq order 0..256.
// ---------------------------------------------------------------------------
__global__ void __launch_bounds__(256) kRowT(const float* __restrict__ filters) {
    __shared__ float2 sh[4][576];
    int tid = threadIdx.x, q = tid & 63, sub = tid >> 6;
    int g = blockIdx.x * 4 + sub;
    int n = g / KF, r0 = g % KF;
    const float* f = filters + (size_t)(n * KF + r0) * KF;
    float2 v[8];
#pragma unroll
    for (int r = 0; r < 8; r++) {
        int c = (q + 64 * r + 7) & 511;
        float val = (c < KF) ? f[c] : 0.0f;
        v[r] = make_float2(val, 0.0f);
    }
    fwd512(v, sh[sub], q);
#pragma unroll
    for (int r = 0; r < 8; r++) sh[sub][PADI(8 * q + r)] = v[r];
    __syncthreads();
    float2* o = g_Tc + (size_t)g * W2;
#pragma unroll
    for (int kk = 0; kk < 5; kk++) {
        int k = q + kk * 64;
        if (k > 256) break;
        o[k] = sh[sub][PADI(brev9(k))];
    }
}

// ---------------------------------------------------------------------------
// 3) kColPair: per tile-pair — register Hermitian unpack of packed Z, forward
//    column FFT, T synthesis + Wiener, inverse column FFT, register re-pack,
//    in-place store to the same slots.
// ---------------------------------------------------------------------------
__global__ void __launch_bounds__(512) kColPair() {
    __shared__ float2 sh[575 * 8];
    __shared__ float ctab[512];
    int tid = threadIdx.x, x = tid & 7, t = tid >> 3;
    ctab[tid] = 2.0f * cosf(PI * (float)tid / 256.0f);

    int n = blockIdx.x / 33, pi = blockIdx.x % 33;
    int a1 = PAIRS[pi].x;
    int c1 = brev6(a1);
    int k;
    if (x < 4) k = 64 * x + c1;
    else {
        int c2 = (64 - c1) & 63;
        k = 64 * (x - 4) + c2;
        if (c1 == 0) k += 64;      // self-pair tile 0: freqs 64..256
    }
    int m  = (512 - k) & 511;
    int pk = 8 * brev6(k & 63) + brev3v(k >> 6);
    int pm = 8 * brev6(m & 63) + brev3v(m >> 6);
    int b = t >> 3, q2 = t & 7;
    int par = t & 1, rp0 = t >> 1;

    // ---- T synthesis for column k (sparse 15-row input) ----
    const float2* tcb = g_Tc + (size_t)n * KF * W2 + k;
    float2 v[8];
#pragma unroll
    for (int r = 0; r < 8; r++) {
        int rr = (t + 64 * r + 7) & 511;
        v[r] = (rr < KF) ? tcb[(size_t)rr * W2] : make_float2(0.0f, 0.0f);
    }
    dif8<true>(v, wang(ANG * (float)t / 256.0f));
#pragma unroll
    for (int r = 0; r < 8; r++) sh[PADI(t + 64 * r) * 8 + x] = v[r];
    __syncthreads();
#pragma unroll
    for (int r = 0; r < 8; r++) v[r] = sh[PADI(64 * b + q2 + 8 * r) * 8 + x];
    dif8<true>(v, wang(ANG * (float)q2 / 32.0f));
#pragma unroll
    for (int r = 0; r < 8; r++) sh[PADI(64 * b + q2 + 8 * r) * 8 + x] = v[r];
    __syncthreads();
    float2 T[8];
#pragma unroll
    for (int r = 0; r < 8; r++) T[r] = sh[PADI(8 * t + r) * 8 + x];
    dif8<false>(T, make_float2(1.0f, 0.0f));

    // ---- Load packed Z (even t: slot pk; odd t: slot pm), share via shfl,
    //      unpack to X[u=t+64r, k] in registers ----
    const float2* Zc = g_Z + (size_t)n * 256 * 512 + (par ? pm : pk);
    float2 A[8];
#pragma unroll
    for (int r = 0; r < 8; r++) A[r] = Zc[(size_t)(rp0 + 32 * r) * 512];
#pragma unroll
    for (int r = 0; r < 8; r++) {
        float bx = __shfl_xor_sync(0xFFFFFFFFu, A[r].x, 8);
        float by = __shfl_xor_sync(0xFFFFFFFFu, A[r].y, 8);
        float zkx = par ? bx : A[r].x, zky = par ? by : A[r].y;
        float zmx = par ? A[r].x : bx, zmy = par ? A[r].y : by;
        // even u: X0 = (Zk + conj(Zm))/2 ; odd u: X1 = (Zk - conj(Zm))/(2i)
        v[r] = par ? make_float2(0.5f * (zky + zmy), 0.5f * (zmx - zkx))
                   : make_float2(0.5f * (zkx + zmx), 0.5f * (zky - zmy));
    }

    // ---- forward column FFT of X ----
    dif8<true>(v, wang(ANG * (float)t / 256.0f));
    __syncthreads();                 // all T reads retired before overwrite
#pragma unroll
    for (int r = 0; r < 8; r++) sh[PADI(t + 64 * r) * 8 + x] = v[r];
    __syncthreads();
#pragma unroll
    for (int r = 0; r < 8; r++) v[r] = sh[PADI(64 * b + q2 + 8 * r) * 8 + x];
    dif8<true>(v, wang(ANG * (float)q2 / 32.0f));
#pragma unroll
    for (int r = 0; r < 8; r++) sh[PADI(64 * b + q2 + 8 * r) * 8 + x] = v[r];
    __syncthreads();
#pragma unroll
    for (int r = 0; r < 8; r++) v[r] = sh[PADI(8 * t + r) * 8 + x];
    dif8<false>(v, make_float2(1.0f, 0.0f));

    // ---- Wiener pointwise (slot 8t+r holds row-freq 64*brev3(r)+brev6(t)) ----
    int kb6 = brev6(t);
    float cj = ctab[k];
#pragma unroll
    for (int r = 0; r < 8; r++) {
        int fr = 64 * brev3v(r) + kb6;
        float reg = 4.0f - ctab[fr] - cj;
        float2 Tv = T[r], Yv = v[r];
        float inv = 1.0f / (Tv.x * Tv.x + Tv.y * Tv.y + BALANCE * reg * reg);
        v[r] = make_float2((Tv.x * Yv.x + Tv.y * Yv.y) * inv,
                           (Tv.x * Yv.y - Tv.y * Yv.x) * inv);
    }

    // ---- inverse column FFT ----
    dit8<false>(v, make_float2(1.0f, 0.0f));
    __syncthreads();
#pragma unroll
    for (int r = 0; r < 8; r++) sh[PADI(8 * t + r) * 8 + x] = v[r];
    __syncthreads();
#pragma unroll
    for (int r = 0; r < 8; r++) v[r] = sh[PADI(64 * b + q2 + 8 * r) * 8 + x];
    dit8<true>(v, wang(-ANG * (float)q2 / 32.0f));
#pragma unroll
    for (int r = 0; r < 8; r++) sh[PADI(64 * b + q2 + 8 * r) * 8 + x] = v[r];
    __syncthreads();
#pragma unroll
    for (int r = 0; r < 8; r++) v[r] = sh[PADI(t + 64 * r) * 8 + x];
    dit8<true>(v, wang(-ANG * (float)t / 256.0f));

    // ---- re-pack: even t -> P = Xf0 + i*Xf1 at slot pk;
    //               odd  t -> Q = conj(Xf0 - i*Xf1) at slot pm (skip k==0) ----
    float2* Zo = g_Z + (size_t)n * 256 * 512 + (par ? pm : pk);
    bool wr = (!par) || (k != 0);
#pragma unroll
    for (int r = 0; r < 8; r++) {
        float bx = __shfl_xor_sync(0xFFFFFFFFu, v[r].x, 8);
        float by = __shfl_xor_sync(0xFFFFFFFFu, v[r].y, 8);
        float2 o = par ? make_float2(bx + v[r].y, v[r].x - by)   // Q (X0=B, X1=v)
                       : make_float2(v[r].x - by, v[r].y + bx);  // P (X0=v, X1=B)
        if (wr) Zo[(size_t)(rp0 + 32 * r) * 512] = o;
    }
}

// ---------------------------------------------------------------------------
// 4) kRowInv: slot-ordered packed Zf IS the bit-reversed DIT input.
//    Coalesced float4 load -> inverse FFT -> scale+clip -> 2 real rows.
// ---------------------------------------------------------------------------
__global__ void __launch_bounds__(256) kRowInv(float* __restrict__ out) {
    __shared__ float2 sh[4][576];
    int tid = threadIdx.x, q = tid & 63, sub = tid >> 6;
    int g = blockIdx.x * 4 + sub;
    int n = g >> 8, rp = g & 255;
    const float4* ib = reinterpret_cast<const float4*>(g_Z + (size_t)g * 512 + 8 * q);
    float2 v[8];
#pragma unroll
    for (int r = 0; r < 4; r++) {
        float4 L = ib[r];
        v[2 * r]     = make_float2(L.x, L.y);
        v[2 * r + 1] = make_float2(L.z, L.w);
    }
    dit8<false>(v, make_float2(1.0f, 0.0f));
#pragma unroll
    for (int r = 0; r < 8; r++) sh[sub][PADI(8 * q + r)] = v[r];
    __syncthreads();
    int b = q >> 3, q2 = q & 7;
#pragma unroll
    for (int r = 0; r < 8; r++) v[r] = sh[sub][PADI(64 * b + q2 + 8 * r)];
    dit8<true>(v, wang(-ANG * (float)q2 / 32.0f));
#pragma unroll
    for (int r = 0; r < 8; r++) sh[sub][PADI(64 * b + q2 + 8 * r)] = v[r];
    __syncthreads();
#pragma unroll
    for (int r = 0; r < 8; r++) v[r] = sh[sub][PADI(q + 64 * r)];
    dit8<true>(v, wang(-ANG * (float)q / 256.0f));
    const float sc = 1.0f / (512.0f * 512.0f);
    float* o0 = out + ((size_t)n * N + 2 * rp) * N;
    float* o1 = o0 + N;
#pragma unroll
    for (int r = 0; r < 8; r++) {
        int i = q + 64 * r;
        o0[i] = fminf(1.0f, fmaxf(-1.0f, v[r].x * sc));
        o1[i] = fminf(1.0f, fmaxf(-1.0f, v[r].y * sc));
    }
}

// ---------------------------------------------------------------------------
extern "C" void kernel_launch(void* const* d_in, const int* in_sizes, int n_in,
                              void* d_out, int out_size) {
    const float* y       = (const float*)d_in[0];
    const float* filters = (const float*)d_in[1];
    float* out = (float*)d_out;

    kRowFwdY<<<NIMG * 64, 256>>>(y);     // packed slot-order spectrum
    kRowT<<<180, 256>>>(filters);        // PSF row spectra
    kColPair<<<NIMG * 33, 512>>>();      // unpack + fwd col + Wiener + inv col + repack
    kRowInv<<<NIMG * 64, 256>>>(out);    // inverse rows from slot order
}

// round 5
// speedup vs baseline: 6.7688x; 1.0869x over previous
#include <cuda_runtime.h>
#include <math.h>

#define NIMG 48
#define N    512
#define KF   15
#define W2   264          // g_Tc padded width (cols 0..256 used)
#define BALANCE 0.1f
#define S2C 0.70710678118654752f
#define PI  3.14159265358979323846f
#define ANG (-3.14159265358979323846f)
#define PADI(n) ((n) + ((n) >> 3))

// Packed spectrum, slot-ordered: g_Z[n][rp][p] = Z[rp, brev9(p)] where
// Z[rp] = FFT(y[2rp] + i*y[2rp+1]).  50.3 MB, updated in place by kColPair.
__device__ __align__(256) float2 g_Z[NIMG * 256 * 512];
__device__ __align__(256) float2 g_Tc[NIMG * KF * W2];   // PSF row spectra

// Tile pairs: mate(a) = brev6(64 - brev6(a)); 2 self-pairs + 31 proper = 33.
__constant__ int2 PAIRS[33] = {
    {0,0},{1,1},{2,3},{4,7},{5,6},{8,15},{9,14},{10,13},{11,12},
    {16,31},{17,30},{18,29},{19,28},{20,27},{21,26},{22,25},{23,24},
    {32,63},{33,62},{34,61},{35,60},{36,59},{37,58},{38,57},{39,56},
    {40,55},{41,54},{42,53},{43,52},{44,51},{45,50},{46,49},{47,48}
};

__device__ __forceinline__ int brev9(int x) { return (int)(__brev((unsigned)x) >> 23); }
__device__ __forceinline__ int brev6(int x) { return (int)(__brev((unsigned)x) >> 26); }
__device__ __forceinline__ int brev3v(int x) { return ((x & 1) << 2) | (x & 2) | (x >> 2); }
__device__ __forceinline__ float2 cmul(float2 a, float2 b) {
    return make_float2(a.x * b.x - a.y * b.y, a.x * b.y + a.y * b.x);
}
__device__ __forceinline__ float2 cadd(float2 a, float2 b) { return make_float2(a.x + b.x, a.y + b.y); }
__device__ __forceinline__ float2 csub(float2 a, float2 b) { return make_float2(a.x - b.x, a.y - b.y); }
// Fast twiddle: args always in [-pi, pi]; __sincosf abs err ~4e-7 (fine vs 1e-3 gate).
__device__ __forceinline__ float2 wang(float a) { float sn, cs; __sincosf(a, &sn, &cs); return make_float2(cs, sn); }

// ---------------------------------------------------------------------------
// Register radix-8 blocks (3 radix-2 stages).
// ---------------------------------------------------------------------------
template <bool TW>
__device__ __forceinline__ void dif8(float2 v[8], float2 w1) {
    float2 w2, w4;
    if (TW) { w2 = cmul(w1, w1); w4 = cmul(w2, w2); }
    float2 t0 = csub(v[0], v[4]); v[0] = cadd(v[0], v[4]);
    float2 t1 = csub(v[1], v[5]); v[1] = cadd(v[1], v[5]);
    float2 t2 = csub(v[2], v[6]); v[2] = cadd(v[2], v[6]);
    float2 t3 = csub(v[3], v[7]); v[3] = cadd(v[3], v[7]);
    t1 = make_float2(S2C * (t1.x + t1.y), S2C * (t1.y - t1.x));
    t2 = make_float2(t2.y, -t2.x);
    t3 = make_float2(S2C * (t3.y - t3.x), -S2C * (t3.x + t3.y));
    if (TW) { t0 = cmul(t0, w1); t1 = cmul(t1, w1); t2 = cmul(t2, w1); t3 = cmul(t3, w1); }
    v[4] = t0; v[5] = t1; v[6] = t2; v[7] = t3;
    float2 t;
    t = csub(v[0], v[2]); v[0] = cadd(v[0], v[2]); if (TW) t = cmul(t, w2); v[2] = t;
    t = csub(v[1], v[3]); v[1] = cadd(v[1], v[3]); t = make_float2(t.y, -t.x); if (TW) t = cmul(t, w2); v[3] = t;
    t = csub(v[4], v[6]); v[4] = cadd(v[4], v[6]); if (TW) t = cmul(t, w2); v[6] = t;
    t = csub(v[5], v[7]); v[5] = cadd(v[5], v[7]); t = make_float2(t.y, -t.x); if (TW) t = cmul(t, w2); v[7] = t;
    t = csub(v[0], v[1]); v[0] = cadd(v[0], v[1]); if (TW) t = cmul(t, w4); v[1] = t;
    t = csub(v[2], v[3]); v[2] = cadd(v[2], v[3]); if (TW) t = cmul(t, w4); v[3] = t;
    t = csub(v[4], v[5]); v[4] = cadd(v[4], v[5]); if (TW) t = cmul(t, w4); v[5] = t;
    t = csub(v[6], v[7]); v[6] = cadd(v[6], v[7]); if (TW) t = cmul(t, w4); v[7] = t;
}

template <bool TW>
__device__ __forceinline__ void dit8(float2 v[8], float2 w1) {
    float2 w2, w4;
    if (TW) { w2 = cmul(w1, w1); w4 = cmul(w2, w2); }
    float2 t;
    t = v[1]; if (TW) t = cmul(t, w4); v[1] = csub(v[0], t); v[0] = cadd(v[0], t);
    t = v[3]; if (TW) t = cmul(t, w4); v[3] = csub(v[2], t); v[2] = cadd(v[2], t);
    t = v[5]; if (TW) t = cmul(t, w4); v[5] = csub(v[4], t); v[4] = cadd(v[4], t);
    t = v[7]; if (TW) t = cmul(t, w4); v[7] = csub(v[6], t); v[6] = cadd(v[6], t);
    t = v[2]; if (TW) t = cmul(t, w2); v[2] = csub(v[0], t); v[0] = cadd(v[0], t);
    t = v[3]; t = make_float2(-t.y, t.x); if (TW) t = cmul(t, w2); v[3] = csub(v[1], t); v[1] = cadd(v[1], t);
    t = v[6]; if (TW) t = cmul(t, w2); v[6] = csub(v[4], t); v[4] = cadd(v[4], t);
    t = v[7]; t = make_float2(-t.y, t.x); if (TW) t = cmul(t, w2); v[7] = csub(v[5], t); v[5] = cadd(v[5], t);
    t = v[4]; if (TW) t = cmul(t, w1); v[4] = csub(v[0], t); v[0] = cadd(v[0], t);
    t = v[5]; t = make_float2(S2C * (t.x - t.y), S2C * (t.x + t.y)); if (TW) t = cmul(t, w1);
    v[5] = csub(v[1], t); v[1] = cadd(v[1], t);
    t = v[6]; t = make_float2(-t.y, t.x); if (TW) t = cmul(t, w1);
    v[6] = csub(v[2], t); v[2] = cadd(v[2], t);
    t = v[7]; t = make_float2(-S2C * (t.x + t.y), S2C * (t.x - t.y)); if (TW) t = cmul(t, w1);
    v[7] = csub(v[3], t); v[3] = cadd(v[3], t);
}

// Forward 512-pt FFT: v enters x[q+64r], exits slot 8q+r (slot p = freq brev9(p)).
__device__ __forceinline__ void fwd512(float2 v[8], float2* sh, int q) {
    dif8<true>(v, wang(ANG * (float)q / 256.0f));
#pragma unroll
    for (int r = 0; r < 8; r++) sh[PADI(q + 64 * r)] = v[r];
    __syncthreads();
    int b = q >> 3, q2 = q & 7;
#pragma unroll
    for (int r = 0; r < 8; r++) v[r] = sh[PADI(64 * b + q2 + 8 * r)];
    dif8<true>(v, wang(ANG * (float)q2 / 32.0f));
#pragma unroll
    for (int r = 0; r < 8; r++) sh[PADI(64 * b + q2 + 8 * r)] = v[r];
    __syncthreads();
#pragma unroll
    for (int r = 0; r < 8; r++) v[r] = sh[PADI(8 * q + r)];
    dif8<false>(v, make_float2(1.0f, 0.0f));
}

// ---------------------------------------------------------------------------
// 1) kRowFwd: merged kernel. Blocks [0, 3072): 2 real y rows per complex FFT,
//    packed slot-order spectrum from registers. Blocks [3072, 3252): PSF row
//    spectra (15 nonzero rows/image), natural freq order 0..256.
// ---------------------------------------------------------------------------
__global__ void __launch_bounds__(256) kRowFwd(const float* __restrict__ y,
                                               const float* __restrict__ filters) {
    __shared__ float2 sh[4][576];
    int tid = threadIdx.x, q = tid & 63, sub = tid >> 6;
    if (blockIdx.x < NIMG * 64) {
        int g = blockIdx.x * 4 + sub;              // global row-pair id
        int n = g >> 8, rp = g & 255;
        const float* y0 = y + ((size_t)n * N + 2 * rp) * N;
        const float* y1 = y0 + N;
        float2 v[8];
#pragma unroll
        for (int r = 0; r < 8; r++) { int i = q + 64 * r; v[r] = make_float2(y0[i], y1[i]); }
        fwd512(v, sh[sub], q);
        float4* o = reinterpret_cast<float4*>(g_Z + (size_t)g * 512 + 8 * q);
#pragma unroll
        for (int r = 0; r < 4; r++)
            o[r] = make_float4(v[2 * r].x, v[2 * r].y, v[2 * r + 1].x, v[2 * r + 1].y);
    } else {
        int g = (blockIdx.x - NIMG * 64) * 4 + sub;   // 0 .. 719
        int n = g / KF, r0 = g % KF;
        const float* f = filters + (size_t)(n * KF + r0) * KF;
        float2 v[8];
#pragma unroll
        for (int r = 0; r < 8; r++) {
            int c = (q + 64 * r + 7) & 511;
            float val = (c < KF) ? f[c] : 0.0f;
            v[r] = make_float2(val, 0.0f);
        }
        fwd512(v, sh[sub], q);
#pragma unroll
        for (int r = 0; r < 8; r++) sh[sub][PADI(8 * q + r)] = v[r];
        __syncthreads();
        float2* o = g_Tc + (size_t)g * W2;
#pragma unroll
        for (int kk = 0; kk < 5; kk++) {
            int k = q + kk * 64;
            if (k > 256) break;
            o[k] = sh[sub][PADI(brev9(k))];
        }
    }
}

// ---------------------------------------------------------------------------
// 2) kColPair: per tile-pair — register Hermitian unpack of packed Z, forward
//    column FFT, T synthesis + Wiener, inverse column FFT, register re-pack,
//    in-place store to the same slots.
// ---------------------------------------------------------------------------
__global__ void __launch_bounds__(512) kColPair() {
    __shared__ float2 sh[575 * 8];
    __shared__ float ctab[512];
    int tid = threadIdx.x, x = tid & 7, t = tid >> 3;
    ctab[tid] = 2.0f * __cosf(PI * (float)tid / 256.0f);

    int n = blockIdx.x / 33, pi = blockIdx.x % 33;
    int a1 = PAIRS[pi].x;
    int c1 = brev6(a1);
    int k;
    if (x < 4) k = 64 * x + c1;
    else {
        int c2 = (64 - c1) & 63;
        k = 64 * (x - 4) + c2;
        if (c1 == 0) k += 64;      // self-pair tile 0: freqs 64..256
    }
    int m  = (512 - k) & 511;
    int pk = 8 * brev6(k & 63) + brev3v(k >> 6);
    int pm = 8 * brev6(m & 63) + brev3v(m >> 6);
    int b = t >> 3, q2 = t & 7;
    int par = t & 1, rp0 = t >> 1;

    // ---- T synthesis for column k (sparse 15-row input) ----
    const float2* tcb = g_Tc + (size_t)n * KF * W2 + k;
    float2 v[8];
#pragma unroll
    for (int r = 0; r < 8; r++) {
        int rr = (t + 64 * r + 7) & 511;
        v[r] = (rr < KF) ? tcb[(size_t)rr * W2] : make_float2(0.0f, 0.0f);
    }
    dif8<true>(v, wang(ANG * (float)t / 256.0f));
#pragma unroll
    for (int r = 0; r < 8; r++) sh[PADI(t + 64 * r) * 8 + x] = v[r];
    __syncthreads();
#pragma unroll
    for (int r = 0; r < 8; r++) v[r] = sh[PADI(64 * b + q2 + 8 * r) * 8 + x];
    dif8<true>(v, wang(ANG * (float)q2 / 32.0f));
#pragma unroll
    for (int r = 0; r < 8; r++) sh[PADI(64 * b + q2 + 8 * r) * 8 + x] = v[r];
    __syncthreads();
    float2 T[8];
#pragma unroll
    for (int r = 0; r < 8; r++) T[r] = sh[PADI(8 * t + r) * 8 + x];
    dif8<false>(T, make_float2(1.0f, 0.0f));

    // ---- Load packed Z (even t: slot pk; odd t: slot pm), share via shfl,
    //      unpack to X[u=t+64r, k] in registers ----
    const float2* Zc = g_Z + (size_t)n * 256 * 512 + (par ? pm : pk);
    float2 A[8];
#pragma unroll
    for (int r = 0; r < 8; r++) A[r] = Zc[(size_t)(rp0 + 32 * r) * 512];
#pragma unroll
    for (int r = 0; r < 8; r++) {
        float bx = __shfl_xor_sync(0xFFFFFFFFu, A[r].x, 8);
        float by = __shfl_xor_sync(0xFFFFFFFFu, A[r].y, 8);
        float zkx = par ? bx : A[r].x, zky = par ? by : A[r].y;
        float zmx = par ? A[r].x : bx, zmy = par ? A[r].y : by;
        // even u: X0 = (Zk + conj(Zm))/2 ; odd u: X1 = (Zk - conj(Zm))/(2i)
        v[r] = par ? make_float2(0.5f * (zky + zmy), 0.5f * (zmx - zkx))
                   : make_float2(0.5f * (zkx + zmx), 0.5f * (zky - zmy));
    }

    // ---- forward column FFT of X ----
    dif8<true>(v, wang(ANG * (float)t / 256.0f));
    __syncthreads();                 // all T reads retired before overwrite
#pragma unroll
    for (int r = 0; r < 8; r++) sh[PADI(t + 64 * r) * 8 + x] = v[r];
    __syncthreads();
#pragma unroll
    for (int r = 0; r < 8; r++) v[r] = sh[PADI(64 * b + q2 + 8 * r) * 8 + x];
    dif8<true>(v, wang(ANG * (float)q2 / 32.0f));
#pragma unroll
    for (int r = 0; r < 8; r++) sh[PADI(64 * b + q2 + 8 * r) * 8 + x] = v[r];
    __syncthreads();
#pragma unroll
    for (int r = 0; r < 8; r++) v[r] = sh[PADI(8 * t + r) * 8 + x];
    dif8<false>(v, make_float2(1.0f, 0.0f));

    // ---- Wiener pointwise (slot 8t+r holds row-freq 64*brev3(r)+brev6(t)) ----
    int kb6 = brev6(t);
    float cj = ctab[k];
#pragma unroll
    for (int r = 0; r < 8; r++) {
        int fr = 64 * brev3v(r) + kb6;
        float reg = 4.0f - ctab[fr] - cj;
        float2 Tv = T[r], Yv = v[r];
        float inv = 1.0f / (Tv.x * Tv.x + Tv.y * Tv.y + BALANCE * reg * reg);
        v[r] = make_float2((Tv.x * Yv.x + Tv.y * Yv.y) * inv,
                           (Tv.x * Yv.y - Tv.y * Yv.x) * inv);
    }

    // ---- inverse column FFT ----
    dit8<false>(v, make_float2(1.0f, 0.0f));
    __syncthreads();
#pragma unroll
    for (int r = 0; r < 8; r++) sh[PADI(8 * t + r) * 8 + x] = v[r];
    __syncthreads();
#pragma unroll
    for (int r = 0; r < 8; r++) v[r] = sh[PADI(64 * b + q2 + 8 * r) * 8 + x];
    dit8<true>(v, wang(-ANG * (float)q2 / 32.0f));
#pragma unroll
    for (int r = 0; r < 8; r++) sh[PADI(64 * b + q2 + 8 * r) * 8 + x] = v[r];
    __syncthreads();
#pragma unroll
    for (int r = 0; r < 8; r++) v[r] = sh[PADI(t + 64 * r) * 8 + x];
    dit8<true>(v, wang(-ANG * (float)t / 256.0f));

    // ---- re-pack: even t -> P = Xf0 + i*Xf1 at slot pk;
    //               odd  t -> Q = conj(Xf0 - i*Xf1) at slot pm (skip k==0) ----
    float2* Zo = g_Z + (size_t)n * 256 * 512 + (par ? pm : pk);
    bool wr = (!par) || (k != 0);
#pragma unroll
    for (int r = 0; r < 8; r++) {
        float bx = __shfl_xor_sync(0xFFFFFFFFu, v[r].x, 8);
        float by = __shfl_xor_sync(0xFFFFFFFFu, v[r].y, 8);
        float2 o = par ? make_float2(bx + v[r].y, v[r].x - by)   // Q (X0=B, X1=v)
                       : make_float2(v[r].x - by, v[r].y + bx);  // P (X0=v, X1=B)
        if (wr) Zo[(size_t)(rp0 + 32 * r) * 512] = o;
    }
}

// ---------------------------------------------------------------------------
// 3) kRowInv: slot-ordered packed Zf IS the bit-reversed DIT input.
//    Coalesced float4 load -> inverse FFT -> scale+clip -> 2 real rows.
// ---------------------------------------------------------------------------
__global__ void __launch_bounds__(256) kRowInv(float* __restrict__ out) {
    __shared__ float2 sh[4][576];
    int tid = threadIdx.x, q = tid & 63, sub = tid >> 6;
    int g = blockIdx.x * 4 + sub;
    int n = g >> 8, rp = g & 255;
    const float4* ib = reinterpret_cast<const float4*>(g_Z + (size_t)g * 512 + 8 * q);
    float2 v[8];
#pragma unroll
    for (int r = 0; r < 4; r++) {
        float4 L = ib[r];
        v[2 * r]     = make_float2(L.x, L.y);
        v[2 * r + 1] = make_float2(L.z, L.w);
    }
    dit8<false>(v, make_float2(1.0f, 0.0f));
#pragma unroll
    for (int r = 0; r < 8; r++) sh[sub][PADI(8 * q + r)] = v[r];
    __syncthreads();
    int b = q >> 3, q2 = q & 7;
#pragma unroll
    for (int r = 0; r < 8; r++) v[r] = sh[sub][PADI(64 * b + q2 + 8 * r)];
    dit8<true>(v, wang(-ANG * (float)q2 / 32.0f));
#pragma unroll
    for (int r = 0; r < 8; r++) sh[sub][PADI(64 * b + q2 + 8 * r)] = v[r];
    __syncthreads();
#pragma unroll
    for (int r = 0; r < 8; r++) v[r] = sh[sub][PADI(q + 64 * r)];
    dit8<true>(v, wang(-ANG * (float)q / 256.0f));
    const float sc = 1.0f / (512.0f * 512.0f);
    float* o0 = out + ((size_t)n * N + 2 * rp) * N;
    float* o1 = o0 + N;
#pragma unroll
    for (int r = 0; r < 8; r++) {
        int i = q + 64 * r;
        o0[i] = fminf(1.0f, fmaxf(-1.0f, v[r].x * sc));
        o1[i] = fminf(1.0f, fmaxf(-1.0f, v[r].y * sc));
    }
}

// ---------------------------------------------------------------------------
extern "C" void kernel_launch(void* const* d_in, const int* in_sizes, int n_in,
                              void* d_out, int out_size) {
    const float* y       = (const float*)d_in[0];
    const float* filters = (const float*)d_in[1];
    float* out = (float*)d_out;

    kRowFwd<<<NIMG * 64 + 180, 256>>>(y, filters);  // y rows + PSF rows merged
    kColPair<<<NIMG * 33, 512>>>();                 // unpack + fwd col + Wiener + inv col + repack
    kRowInv<<<NIMG * 64, 256>>>(out);               // inverse rows from slot order
}

// round 6
// speedup vs baseline: 6.9185x; 1.0221x over previous
#include <cuda_runtime.h>
#include <math.h>

#define NIMG 48
#define N    512
#define KF   15
#define BALANCE 0.1f
#define S2C 0.70710678118654752f
#define PI  3.14159265358979323846f
#define ANG (-3.14159265358979323846f)
#define PADI(n) ((n) + ((n) >> 3))

// Packed spectrum, slot-ordered: g_Z[n][rp][p] = Z[rp, brev9(p)] where
// Z[rp] = FFT(y[2rp] + i*y[2rp+1]).  50.3 MB, updated in place by kColPair.
__device__ __align__(256) float2 g_Z[NIMG * 256 * 512];

// First tile of each Hermitian tile pair (mate(a) = brev6(64 - brev6(a))).
__constant__ int PAIR_A[33] = {0,1,2,4,5,8,9,10,11,16,17,18,19,20,21,22,23,
                               32,33,34,35,36,37,38,39,40,41,42,43,44,45,46,47};

__device__ __forceinline__ int brev6(int x) { return (int)(__brev((unsigned)x) >> 26); }
__device__ __forceinline__ int brev3v(int x) { return ((x & 1) << 2) | (x & 2) | (x >> 2); }
__device__ __forceinline__ float2 cmul(float2 a, float2 b) {
    return make_float2(a.x * b.x - a.y * b.y, a.x * b.y + a.y * b.x);
}
__device__ __forceinline__ float2 cadd(float2 a, float2 b) { return make_float2(a.x + b.x, a.y + b.y); }
__device__ __forceinline__ float2 csub(float2 a, float2 b) { return make_float2(a.x - b.x, a.y - b.y); }
__device__ __forceinline__ float2 wang(float a) { float sn, cs; __sincosf(a, &sn, &cs); return make_float2(cs, sn); }

// ---------------------------------------------------------------------------
// Register radix-8 blocks (3 radix-2 stages).
// ---------------------------------------------------------------------------
template <bool TW>
__device__ __forceinline__ void dif8(float2 v[8], float2 w1) {
    float2 w2, w4;
    if (TW) { w2 = cmul(w1, w1); w4 = cmul(w2, w2); }
    float2 t0 = csub(v[0], v[4]); v[0] = cadd(v[0], v[4]);
    float2 t1 = csub(v[1], v[5]); v[1] = cadd(v[1], v[5]);
    float2 t2 = csub(v[2], v[6]); v[2] = cadd(v[2], v[6]);
    float2 t3 = csub(v[3], v[7]); v[3] = cadd(v[3], v[7]);
    t1 = make_float2(S2C * (t1.x + t1.y), S2C * (t1.y - t1.x));
    t2 = make_float2(t2.y, -t2.x);
    t3 = make_float2(S2C * (t3.y - t3.x), -S2C * (t3.x + t3.y));
    if (TW) { t0 = cmul(t0, w1); t1 = cmul(t1, w1); t2 = cmul(t2, w1); t3 = cmul(t3, w1); }
    v[4] = t0; v[5] = t1; v[6] = t2; v[7] = t3;
    float2 t;
    t = csub(v[0], v[2]); v[0] = cadd(v[0], v[2]); if (TW) t = cmul(t, w2); v[2] = t;
    t = csub(v[1], v[3]); v[1] = cadd(v[1], v[3]); t = make_float2(t.y, -t.x); if (TW) t = cmul(t, w2); v[3] = t;
    t = csub(v[4], v[6]); v[4] = cadd(v[4], v[6]); if (TW) t = cmul(t, w2); v[6] = t;
    t = csub(v[5], v[7]); v[5] = cadd(v[5], v[7]); t = make_float2(t.y, -t.x); if (TW) t = cmul(t, w2); v[7] = t;
    t = csub(v[0], v[1]); v[0] = cadd(v[0], v[1]); if (TW) t = cmul(t, w4); v[1] = t;
    t = csub(v[2], v[3]); v[2] = cadd(v[2], v[3]); if (TW) t = cmul(t, w4); v[3] = t;
    t = csub(v[4], v[5]); v[4] = cadd(v[4], v[5]); if (TW) t = cmul(t, w4); v[5] = t;
    t = csub(v[6], v[7]); v[6] = cadd(v[6], v[7]); if (TW) t = cmul(t, w4); v[7] = t;
}

template <bool TW>
__device__ __forceinline__ void dit8(float2 v[8], float2 w1) {
    float2 w2, w4;
    if (TW) { w2 = cmul(w1, w1); w4 = cmul(w2, w2); }
    float2 t;
    t = v[1]; if (TW) t = cmul(t, w4); v[1] = csub(v[0], t); v[0] = cadd(v[0], t);
    t = v[3]; if (TW) t = cmul(t, w4); v[3] = csub(v[2], t); v[2] = cadd(v[2], t);
    t = v[5]; if (TW) t = cmul(t, w4); v[5] = csub(v[4], t); v[4] = cadd(v[4], t);
    t = v[7]; if (TW) t = cmul(t, w4); v[7] = csub(v[6], t); v[6] = cadd(v[6], t);
    t = v[2]; if (TW) t = cmul(t, w2); v[2] = csub(v[0], t); v[0] = cadd(v[0], t);
    t = v[3]; t = make_float2(-t.y, t.x); if (TW) t = cmul(t, w2); v[3] = csub(v[1], t); v[1] = cadd(v[1], t);
    t = v[6]; if (TW) t = cmul(t, w2); v[6] = csub(v[4], t); v[4] = cadd(v[4], t);
    t = v[7]; t = make_float2(-t.y, t.x); if (TW) t = cmul(t, w2); v[7] = csub(v[5], t); v[5] = cadd(v[5], t);
    t = v[4]; if (TW) t = cmul(t, w1); v[4] = csub(v[0], t); v[0] = cadd(v[0], t);
    t = v[5]; t = make_float2(S2C * (t.x - t.y), S2C * (t.x + t.y)); if (TW) t = cmul(t, w1);
    v[5] = csub(v[1], t); v[1] = cadd(v[1], t);
    t = v[6]; t = make_float2(-t.y, t.x); if (TW) t = cmul(t, w1);
    v[6] = csub(v[2], t); v[2] = cadd(v[2], t);
    t = v[7]; t = make_float2(-S2C * (t.x + t.y), S2C * (t.x - t.y)); if (TW) t = cmul(t, w1);
    v[7] = csub(v[3], t); v[3] = cadd(v[3], t);
}

// Forward 512-pt FFT: v enters x[q+64r], exits slot 8q+r (slot p = freq brev9(p)).
__device__ __forceinline__ void fwd512(float2 v[8], float2* sh, int q) {
    dif8<true>(v, wang(ANG * (float)q / 256.0f));
#pragma unroll
    for (int r = 0; r < 8; r++) sh[PADI(q + 64 * r)] = v[r];
    __syncthreads();
    int b = q >> 3, q2 = q & 7;
#pragma unroll
    for (int r = 0; r < 8; r++) v[r] = sh[PADI(64 * b + q2 + 8 * r)];
    dif8<true>(v, wang(ANG * (float)q2 / 32.0f));
#pragma unroll
    for (int r = 0; r < 8; r++) sh[PADI(64 * b + q2 + 8 * r)] = v[r];
    __syncthreads();
#pragma unroll
    for (int r = 0; r < 8; r++) v[r] = sh[PADI(8 * q + r)];
    dif8<false>(v, make_float2(1.0f, 0.0f));
}

// ---------------------------------------------------------------------------
// 1) kRowFwdY: 2 real y rows per complex FFT, packed slot-order spectrum
//    stored straight from registers (float4, fully coalesced).
// ---------------------------------------------------------------------------
__global__ void __launch_bounds__(256) kRowFwdY(const float* __restrict__ y) {
    __shared__ float2 sh[4][576];
    int tid = threadIdx.x, q = tid & 63, sub = tid >> 6;
    int g = blockIdx.x * 4 + sub;              // global row-pair id
    int n = g >> 8, rp = g & 255;
    const float* y0 = y + ((size_t)n * N + 2 * rp) * N;
    const float* y1 = y0 + N;
    float2 v[8];
#pragma unroll
    for (int r = 0; r < 8; r++) { int i = q + 64 * r; v[r] = make_float2(y0[i], y1[i]); }
    fwd512(v, sh[sub], q);
    float4* o = reinterpret_cast<float4*>(g_Z + (size_t)g * 512 + 8 * q);
#pragma unroll
    for (int r = 0; r < 4; r++)
        o[r] = make_float4(v[2 * r].x, v[2 * r].y, v[2 * r + 1].x, v[2 * r + 1].y);
}

// ---------------------------------------------------------------------------
// 2) kColPair: per tile-pair. PSF row spectra G_t(k) computed in-kernel
//    (15-term sparse DFT), T column spectrum synthesized in registers via
//    fold + 8-pt DFT (no smem FFT), Y Hermitian-unpacked via shfl, forward
//    column FFT, Wiener, inverse column FFT, repack, in-place store.
// ---------------------------------------------------------------------------
__global__ void __launch_bounds__(512) kColPair(const float* __restrict__ filters) {
    __shared__ float2 sh[575 * 8];
    __shared__ float2 Gsh[KF * 8];
    __shared__ float ctab[512];
    int tid = threadIdx.x, x = tid & 7, t = tid >> 3;
    ctab[tid] = 2.0f * __cosf(PI * (float)tid / 256.0f);

    int n = blockIdx.x / 33, pi = blockIdx.x % 33;
    int c1 = brev6(PAIR_A[pi]);
    int k;
    if (x < 4) k = 64 * x + c1;
    else {
        int c2 = (64 - c1) & 63;
        k = 64 * (x - 4) + c2;
        if (c1 == 0) k += 64;      // self-pair tile 0: freqs 64..256
    }
    int m  = (512 - k) & 511;
    int pk = 8 * brev6(k & 63) + brev3v(k >> 6);
    int pm = 8 * brev6(m & 63) + brev3v(m >> 6);
    int b = t >> 3, q2 = t & 7;
    int par = t & 1, rp0 = t >> 1;
    int kb6 = brev6(t);

    // ---- G_t(k) = sum_c f[t][c] * W^{k(c-7)}  (threads t < 15) ----
    if (t < KF) {
        const float* f = filters + (size_t)(n * KF + t) * KF;
        float2 w1 = wang(ANG * (float)k / 256.0f);
        float2 wp = w1;
        float2 acc = make_float2(f[7], 0.0f);
#pragma unroll
        for (int d = 1; d <= 7; d++) {
            float a = f[7 + d], c = f[7 - d];
            acc.x += (a + c) * wp.x;
            acc.y += (a - c) * wp.y;
            if (d < 7) wp = cmul(wp, w1);
        }
        Gsh[t * 8 + x] = acc;
    }
    __syncthreads();

    // ---- T column synthesis in registers: fold 15 sparse rows to 8 values,
    //      then one 8-pt DFT. T[r] = T(64*brev3(r) + kb6), matching slots. ----
    float2 T[8];
    {
        int a8 = (kb6 * 8) & 511; if (a8 > 256) a8 -= 512;
        float2 W1 = wang(ANG * (float)kb6 / 256.0f);
        float2 W8 = wang(ANG * (float)a8 / 256.0f);
        float2 wf = W1;
        T[0] = Gsh[7 * 8 + x];
#pragma unroll
        for (int e = 1; e < 8; e++) {
            float2 a  = Gsh[(e + 7) * 8 + x];
            float2 bb = Gsh[(e - 1) * 8 + x];
            // wc = W1^(8-e) = W8 * conj(wf);  h[e] = a*wf + bb*conj(wc)
            float2 wc = make_float2(W8.x * wf.x + W8.y * wf.y,
                                    W8.y * wf.x - W8.x * wf.y);
            T[e] = make_float2(a.x * wf.x - a.y * wf.y + bb.x * wc.x + bb.y * wc.y,
                               a.x * wf.y + a.y * wf.x + bb.y * wc.x - bb.x * wc.y);
            if (e < 7) wf = cmul(wf, W1);
        }
        dif8<false>(T, make_float2(1.0f, 0.0f));
    }

    // ---- Load packed Z (even t: slot pk; odd t: slot pm), share via shfl,
    //      unpack to X[u=t+64r, k] in registers ----
    const float2* Zc = g_Z + (size_t)n * 256 * 512 + (par ? pm : pk);
    float2 A[8];
#pragma unroll
    for (int r = 0; r < 8; r++) A[r] = Zc[(size_t)(rp0 + 32 * r) * 512];
    float2 v[8];
#pragma unroll
    for (int r = 0; r < 8; r++) {
        float bx = __shfl_xor_sync(0xFFFFFFFFu, A[r].x, 8);
        float by = __shfl_xor_sync(0xFFFFFFFFu, A[r].y, 8);
        float zkx = par ? bx : A[r].x, zky = par ? by : A[r].y;
        float zmx = par ? A[r].x : bx, zmy = par ? A[r].y : by;
        v[r] = par ? make_float2(0.5f * (zky + zmy), 0.5f * (zmx - zkx))
                   : make_float2(0.5f * (zkx + zmx), 0.5f * (zky - zmy));
    }

    // ---- forward column FFT of X ----
    dif8<true>(v, wang(ANG * (float)t / 256.0f));
#pragma unroll
    for (int r = 0; r < 8; r++) sh[PADI(t + 64 * r) * 8 + x] = v[r];
    __syncthreads();
#pragma unroll
    for (int r = 0; r < 8; r++) v[r] = sh[PADI(64 * b + q2 + 8 * r) * 8 + x];
    dif8<true>(v, wang(ANG * (float)q2 / 32.0f));
#pragma unroll
    for (int r = 0; r < 8; r++) sh[PADI(64 * b + q2 + 8 * r) * 8 + x] = v[r];
    __syncthreads();
#pragma unroll
    for (int r = 0; r < 8; r++) v[r] = sh[PADI(8 * t + r) * 8 + x];
    dif8<false>(v, make_float2(1.0f, 0.0f));

    // ---- Wiener pointwise (slot 8t+r holds row-freq 64*brev3(r)+kb6) ----
    float cj = ctab[k];
#pragma unroll
    for (int r = 0; r < 8; r++) {
        int fr = 64 * brev3v(r) + kb6;
        float reg = 4.0f - ctab[fr] - cj;
        float2 Tv = T[r], Yv = v[r];
        float inv = 1.0f / (Tv.x * Tv.x + Tv.y * Tv.y + BALANCE * reg * reg);
        v[r] = make_float2((Tv.x * Yv.x + Tv.y * Yv.y) * inv,
                           (Tv.x * Yv.y - Tv.y * Yv.x) * inv);
    }

    // ---- inverse column FFT ----
    dit8<false>(v, make_float2(1.0f, 0.0f));
#pragma unroll
    for (int r = 0; r < 8; r++) sh[PADI(8 * t + r) * 8 + x] = v[r];
    __syncthreads();
#pragma unroll
    for (int r = 0; r < 8; r++) v[r] = sh[PADI(64 * b + q2 + 8 * r) * 8 + x];
    dit8<true>(v, wang(-ANG * (float)q2 / 32.0f));
#pragma unroll
    for (int r = 0; r < 8; r++) sh[PADI(64 * b + q2 + 8 * r) * 8 + x] = v[r];
    __syncthreads();
#pragma unroll
    for (int r = 0; r < 8; r++) v[r] = sh[PADI(t + 64 * r) * 8 + x];
    dit8<true>(v, wang(-ANG * (float)t / 256.0f));

    // ---- re-pack: even t -> P = Xf0 + i*Xf1 at slot pk;
    //               odd  t -> Q = conj(Xf0 - i*Xf1) at slot pm (skip k==0) ----
    float2* Zo = g_Z + (size_t)n * 256 * 512 + (par ? pm : pk);
    bool wr = (!par) || (k != 0);
#pragma unroll
    for (int r = 0; r < 8; r++) {
        float bx = __shfl_xor_sync(0xFFFFFFFFu, v[r].x, 8);
        float by = __shfl_xor_sync(0xFFFFFFFFu, v[r].y, 8);
        float2 o = par ? make_float2(bx + v[r].y, v[r].x - by)
                       : make_float2(v[r].x - by, v[r].y + bx);
        if (wr) Zo[(size_t)(rp0 + 32 * r) * 512] = o;
    }
}

// ---------------------------------------------------------------------------
// 3) kRowInv: slot-ordered packed Zf IS the bit-reversed DIT input.
//    Coalesced float4 load -> inverse FFT -> scale+clip -> 2 real rows.
// ---------------------------------------------------------------------------
__global__ void __launch_bounds__(256) kRowInv(float* __restrict__ out) {
    __shared__ float2 sh[4][576];
    int tid = threadIdx.x, q = tid & 63, sub = tid >> 6;
    int g = blockIdx.x * 4 + sub;
    int n = g >> 8, rp = g & 255;
    const float4* ib = reinterpret_cast<const float4*>(g_Z + (size_t)g * 512 + 8 * q);
    float2 v[8];
#pragma unroll
    for (int r = 0; r < 4; r++) {
        float4 L = ib[r];
        v[2 * r]     = make_float2(L.x, L.y);
        v[2 * r + 1] = make_float2(L.z, L.w);
    }
    dit8<false>(v, make_float2(1.0f, 0.0f));
#pragma unroll
    for (int r = 0; r < 8; r++) sh[sub][PADI(8 * q + r)] = v[r];
    __syncthreads();
    int b = q >> 3, q2 = q & 7;
#pragma unroll
    for (int r = 0; r < 8; r++) v[r] = sh[sub][PADI(64 * b + q2 + 8 * r)];
    dit8<true>(v, wang(-ANG * (float)q2 / 32.0f));
#pragma unroll
    for (int r = 0; r < 8; r++) sh[sub][PADI(64 * b + q2 + 8 * r)] = v[r];
    __syncthreads();
#pragma unroll
    for (int r = 0; r < 8; r++) v[r] = sh[sub][PADI(q + 64 * r)];
    dit8<true>(v, wang(-ANG * (float)q / 256.0f));
    const float sc = 1.0f / (512.0f * 512.0f);
    float* o0 = out + ((size_t)n * N + 2 * rp) * N;
    float* o1 = o0 + N;
#pragma unroll
    for (int r = 0; r < 8; r++) {
        int i = q + 64 * r;
        o0[i] = fminf(1.0f, fmaxf(-1.0f, v[r].x * sc));
        o1[i] = fminf(1.0f, fmaxf(-1.0f, v[r].y * sc));
    }
}

// ---------------------------------------------------------------------------
extern "C" void kernel_launch(void* const* d_in, const int* in_sizes, int n_in,
                              void* d_out, int out_size) {
    const float* y       = (const float*)d_in[0];
    const float* filters = (const float*)d_in[1];
    float* out = (float*)d_out;

    kRowFwdY<<<NIMG * 64, 256>>>(y);          // packed slot-order spectrum
    kColPair<<<NIMG * 33, 512>>>(filters);    // G + T synth + fwd col + Wiener + inv col
    kRowInv<<<NIMG * 64, 256>>>(out);         // inverse rows from slot order
}